// round 15
// baseline (speedup 1.0000x reference)
#include <cuda_runtime.h>
#include <cuda_fp16.h>
#include <math.h>
#include <stdint.h>

#define Nn 50000
#define Ee 800000
#define Hh 128
#define Gg 128
#define NSCAN_BLK 49        // ceil(50000/1024)
#define NTILE 391           // ceil(50000/128)
#define NG2 196             // persistent gemm grid: each CTA does 2 tiles
#define NWCAT (5 * 256 * 128)
#define APITCH 136          // 128 + 8 halves pad: conflict-free ldmatrix

// ---------------- scratch (allocation-free: __device__ globals) --------------
__device__ __half g_hh[Nn * Hh];      // fp16 activations (in-place across layers)
__device__ __half g_aggh[Nn * Hh];    // fp16 agg
__device__ __half g_wcat[NWCAT];      // fp16 [layer][k=256][n=128]
__device__ float  g_invdeg[Nn];
__device__ int    g_cntn[Nn];
__device__ int    g_scan[Nn];
__device__ int    g_bsum[NSCAN_BLK];
__device__ int    g_rowptr[Nn + 1];
__device__ int    g_cursor[Nn];
__device__ int    g_srcidx[Ee];

struct WPtrs { const float* p[10]; };

// ---------------- PTX wrappers -------------------------------------------------
__device__ __forceinline__ uint32_t smem_u32(const void* p) {
    uint32_t a;
    asm("{ .reg .u64 t; cvta.to.shared.u64 t, %1; cvt.u32.u64 %0, t; }"
        : "=r"(a) : "l"(p));
    return a;
}
__device__ __forceinline__ void ldsm_x4(uint32_t& r0, uint32_t& r1,
                                        uint32_t& r2, uint32_t& r3, uint32_t addr) {
    asm volatile("ldmatrix.sync.aligned.m8n8.x4.shared.b16 {%0,%1,%2,%3}, [%4];"
                 : "=r"(r0), "=r"(r1), "=r"(r2), "=r"(r3) : "r"(addr));
}
__device__ __forceinline__ void ldsm_x4t(uint32_t& r0, uint32_t& r1,
                                         uint32_t& r2, uint32_t& r3, uint32_t addr) {
    asm volatile("ldmatrix.sync.aligned.m8n8.x4.trans.shared.b16 {%0,%1,%2,%3}, [%4];"
                 : "=r"(r0), "=r"(r1), "=r"(r2), "=r"(r3) : "r"(addr));
}
__device__ __forceinline__ void mma16816(float* d, const uint32_t* a,
                                         uint32_t b0, uint32_t b1) {
    asm volatile(
        "mma.sync.aligned.m16n8k16.row.col.f32.f16.f16.f32 "
        "{%0,%1,%2,%3}, {%4,%5,%6,%7}, {%8,%9}, {%0,%1,%2,%3};"
        : "+f"(d[0]), "+f"(d[1]), "+f"(d[2]), "+f"(d[3])
        : "r"(a[0]), "r"(a[1]), "r"(a[2]), "r"(a[3]), "r"(b0), "r"(b1));
}

// ---------------- prep: x->fp16 + Wcat fp16 (side stream) ------------------------
__global__ void prep_kernel(const float* __restrict__ x, WPtrs wp) {
    int i = blockIdx.x * blockDim.x + threadIdx.x;
    if (i < Nn * Hh / 2) {
        float2 v = reinterpret_cast<const float2*>(x)[i];
        reinterpret_cast<__half2*>(g_hh)[i] = __floats2half2_rn(v.x, v.y);
    }
    if (i < NWCAT) {
        int l = i >> 15;
        int rem = i & 32767;
        int k = rem >> 7, n = rem & 127;
        const float* W = (k < 128) ? wp.p[2 * l] : wp.p[2 * l + 1];
        g_wcat[i] = __float2half_rn(W[(k & 127) * 128 + n]);
    }
}

// ---------------- CSR build (exact R10 versions) ----------------------------------
__global__ void hist_kernel(const int4* __restrict__ el2) {
    int t = blockIdx.x * blockDim.x + threadIdx.x;
    if (t < Ee / 2) {
        int4 e2 = el2[t];       // two edges: (x,y),(z,w)
        atomicAdd(&g_cntn[e2.y], 1);
        atomicAdd(&g_cntn[e2.w], 1);
    }
}
__global__ void scan1_kernel() {
    __shared__ int sh[1024];
    int tid = threadIdx.x;
    int i = blockIdx.x * 1024 + tid;
    int v = (i < Nn) ? g_cntn[i] : 0;
    sh[tid] = v;
    __syncthreads();
    for (int off = 1; off < 1024; off <<= 1) {
        int t = (tid >= off) ? sh[tid - off] : 0;
        __syncthreads();
        sh[tid] += t;
        __syncthreads();
    }
    if (i < Nn) g_scan[i] = sh[tid];
    if (tid == 1023) g_bsum[blockIdx.x] = sh[1023];
}
__global__ void scan3_kernel() {
    __shared__ int soff[NSCAN_BLK + 1];
    int tid = threadIdx.x;
    if (tid == 0) {
        int run = 0;
        for (int b = 0; b < NSCAN_BLK; b++) { soff[b] = run; run += g_bsum[b]; }
    }
    __syncthreads();
    int i = blockIdx.x * blockDim.x + tid;
    if (i < Nn) {
        int v = g_cntn[i];
        int excl = g_scan[i] - v + soff[i >> 10];
        g_rowptr[i] = excl;
        g_cursor[i] = excl;
        g_invdeg[i] = 1.0f / fmaxf((float)v, 1.0f);
    }
    if (i == 0) g_rowptr[Nn] = Ee;
}
__global__ void fill_kernel(const int4* __restrict__ el2) {
    int t = blockIdx.x * blockDim.x + threadIdx.x;
    if (t < Ee / 2) {
        int4 e2 = el2[t];
        int p0 = atomicAdd(&g_cursor[e2.y], 1);
        g_srcidx[p0] = e2.x;
        int p1 = atomicAdd(&g_cursor[e2.w], 1);
        g_srcidx[p1] = e2.z;
    }
}

// ---------------- neighbor gather: 16 lanes x 16B per row (R10 exact) -------------
__device__ __forceinline__ void acc_add8(float* a, uint4 v) {
    __half2 h0 = *reinterpret_cast<__half2*>(&v.x);
    __half2 h1 = *reinterpret_cast<__half2*>(&v.y);
    __half2 h2 = *reinterpret_cast<__half2*>(&v.z);
    __half2 h3 = *reinterpret_cast<__half2*>(&v.w);
    float2 f0 = __half22float2(h0), f1 = __half22float2(h1);
    float2 f2 = __half22float2(h2), f3 = __half22float2(h3);
    a[0] += f0.x; a[1] += f0.y; a[2] += f1.x; a[3] += f1.y;
    a[4] += f2.x; a[5] += f2.y; a[6] += f3.x; a[7] += f3.y;
}
__global__ void __launch_bounds__(256)
gather_kernel(const __half* __restrict__ hh) {
    int t = blockIdx.x * blockDim.x + threadIdx.x;
    int node = t >> 4;
    if (node >= Nn) return;
    int lane16 = t & 15;

    int beg = g_rowptr[node], end = g_rowptr[node + 1];
    float acc[8] = {0.f, 0.f, 0.f, 0.f, 0.f, 0.f, 0.f, 0.f};
    int i = beg;
    for (; i + 3 < end; i += 4) {
        int s0 = g_srcidx[i],     s1 = g_srcidx[i + 1];
        int s2 = g_srcidx[i + 2], s3 = g_srcidx[i + 3];
        uint4 v0 = reinterpret_cast<const uint4*>(hh + (size_t)s0 * Hh)[lane16];
        uint4 v1 = reinterpret_cast<const uint4*>(hh + (size_t)s1 * Hh)[lane16];
        uint4 v2 = reinterpret_cast<const uint4*>(hh + (size_t)s2 * Hh)[lane16];
        uint4 v3 = reinterpret_cast<const uint4*>(hh + (size_t)s3 * Hh)[lane16];
        acc_add8(acc, v0); acc_add8(acc, v1); acc_add8(acc, v2); acc_add8(acc, v3);
    }
    for (; i < end; i++) {
        uint4 v0 = reinterpret_cast<const uint4*>(hh + (size_t)g_srcidx[i] * Hh)[lane16];
        acc_add8(acc, v0);
    }
    float inv = g_invdeg[node];
    __half2 p0 = __floats2half2_rn(acc[0] * inv, acc[1] * inv);
    __half2 p1 = __floats2half2_rn(acc[2] * inv, acc[3] * inv);
    __half2 p2 = __floats2half2_rn(acc[4] * inv, acc[5] * inv);
    __half2 p3 = __floats2half2_rn(acc[6] * inv, acc[7] * inv);
    uint4 u;
    u.x = *reinterpret_cast<uint32_t*>(&p0);
    u.y = *reinterpret_cast<uint32_t*>(&p1);
    u.z = *reinterpret_cast<uint32_t*>(&p2);
    u.w = *reinterpret_cast<uint32_t*>(&p3);
    reinterpret_cast<uint4*>(g_aggh + (size_t)node * Hh)[lane16] = u;
}

// ---------------- persistent 2-tile tensor-core GEMM ------------------------------
// grid = 196; CTA b handles tiles b and b+196 (single wave, weights loaded once).
// smem: As (reloaded per stage) + Wls + Wrs (loaded once) = 104448 B.
__global__ void __launch_bounds__(256, 2)
gemm_mma(const __half* __restrict__ Ah, const __half* __restrict__ Hf,
         const __half* __restrict__ Wc, const float* __restrict__ bias,
         __half* __restrict__ Hout) {
    extern __shared__ __half smem[];
    __half* As  = smem;                     // [128][APITCH]
    __half* Wls = smem + 128 * APITCH;      // [128][APITCH]
    __half* Wrs = smem + 2 * 128 * APITCH;  // [128][APITCH]
    __shared__ float sbias[128];

    int tid = threadIdx.x;
    int lane = tid & 31;
    int wid = tid >> 5;
    int wrow = wid & 3;
    int wcol = wid >> 2;

    if (tid < 128) sbias[tid] = bias[tid];

    uint32_t as_u  = smem_u32(As);
    uint32_t wls_u = smem_u32(Wls);
    uint32_t wrs_u = smem_u32(Wrs);

    // load both weight tiles once (coalesced uint4)
#pragma unroll
    for (int rep = 0; rep < 8; rep++) {
        int c = tid + rep * 256;
        int r = c >> 4, c8 = c & 15;
        *reinterpret_cast<uint4*>(Wls + r * APITCH + c8 * 8) =
            *reinterpret_cast<const uint4*>(Wc + (size_t)r * 128 + c8 * 8);
        *reinterpret_cast<uint4*>(Wrs + r * APITCH + c8 * 8) =
            *reinterpret_cast<const uint4*>(Wc + (size_t)(128 + r) * 128 + c8 * 8);
    }

    for (int t = 0; t < 2; t++) {
        int tile = blockIdx.x + t * NG2;
        if (tile >= NTILE) break;            // uniform per CTA
        int n0 = tile * 128;

        float acc[2][8][4];
#pragma unroll
        for (int mt = 0; mt < 2; mt++)
#pragma unroll
            for (int nt = 0; nt < 8; nt++)
#pragma unroll
                for (int q = 0; q < 4; q++) acc[mt][nt][q] = 0.f;

#pragma unroll
        for (int s = 0; s < 2; s++) {
            const __half* Asrc = s ? Hf : Ah;
            uint32_t w_u = s ? wrs_u : wls_u;
            __syncthreads();   // As free (prev stage / prev tile done reading)
#pragma unroll
            for (int rep = 0; rep < 8; rep++) {
                int c = tid + rep * 256;
                int r = c >> 4, c8 = c & 15;
                int n = n0 + r; if (n >= Nn) n = Nn - 1;
                *reinterpret_cast<uint4*>(As + r * APITCH + c8 * 8) =
                    *reinterpret_cast<const uint4*>(Asrc + (size_t)n * 128 + c8 * 8);
            }
            __syncthreads();

#pragma unroll
            for (int kc = 0; kc < 8; kc++) {
                int k0 = kc * 16;
                uint32_t a[2][4];
#pragma unroll
                for (int mt = 0; mt < 2; mt++) {
                    int r = wrow * 32 + mt * 16 + (lane & 15);
                    uint32_t addr = as_u + (uint32_t)(r * APITCH + k0 + (lane >> 4) * 8) * 2;
                    ldsm_x4(a[mt][0], a[mt][1], a[mt][2], a[mt][3], addr);
                }
#pragma unroll
                for (int nt2 = 0; nt2 < 4; nt2++) {
                    int kr = k0 + (lane & 15);
                    int nc = wcol * 64 + nt2 * 16 + (lane >> 4) * 8;
                    uint32_t addr = w_u + (uint32_t)(kr * APITCH + nc) * 2;
                    uint32_t b0, b1, b2, b3;
                    ldsm_x4t(b0, b1, b2, b3, addr);
#pragma unroll
                    for (int mt = 0; mt < 2; mt++) {
                        mma16816(acc[mt][nt2 * 2],     a[mt], b0, b1);
                        mma16816(acc[mt][nt2 * 2 + 1], a[mt], b2, b3);
                    }
                }
            }
        }

        // epilogue: bias + relu -> fp16 (in-place safe: tile read-set == write-set)
#pragma unroll
        for (int mt = 0; mt < 2; mt++) {
            int r0 = n0 + wrow * 32 + mt * 16 + (lane >> 2);
#pragma unroll
            for (int nt = 0; nt < 8; nt++) {
                int col = wcol * 64 + nt * 8 + (lane & 3) * 2;
                float b0 = sbias[col], b1 = sbias[col + 1];
                float v0 = fmaxf(acc[mt][nt][0] + b0, 0.f);
                float v1 = fmaxf(acc[mt][nt][1] + b1, 0.f);
                float v2 = fmaxf(acc[mt][nt][2] + b0, 0.f);
                float v3 = fmaxf(acc[mt][nt][3] + b1, 0.f);
                if (r0 < Nn)
                    *reinterpret_cast<__half2*>(Hout + (size_t)r0 * 128 + col) =
                        __floats2half2_rn(v0, v1);
                if (r0 + 8 < Nn)
                    *reinterpret_cast<__half2*>(Hout + (size_t)(r0 + 8) * 128 + col) =
                        __floats2half2_rn(v2, v3);
            }
        }
    }
}

// ---------------- fused pool + MLP head: one block per graph ----------------------
__global__ void pool_mlp_kernel(const __half* __restrict__ h,
                                const int* __restrict__ batch,
                                const float* __restrict__ Wf1,
                                const float* __restrict__ bf1,
                                const float* __restrict__ Wf2,
                                const float* __restrict__ bf2,
                                float* __restrict__ out) {
    __shared__ int sbeg, send;
    __shared__ float gs[128];
    __shared__ float red[128];
    int g = blockIdx.x;
    int j = threadIdx.x;
    if (j == 0) {
        int lo = 0, hi = Nn;
        while (lo < hi) { int mid = (lo + hi) >> 1; if (batch[mid] < g) lo = mid + 1; else hi = mid; }
        sbeg = lo;
        lo = 0; hi = Nn;
        while (lo < hi) { int mid = (lo + hi) >> 1; if (batch[mid] < g + 1) lo = mid + 1; else hi = mid; }
        send = lo;
    }
    __syncthreads();
    int beg = sbeg, end = send;
    float acc = 0.f;
    int r = beg;
    for (; r + 3 < end; r += 4) {
        acc += __half2float(h[(size_t)r * 128 + j]);
        acc += __half2float(h[(size_t)(r + 1) * 128 + j]);
        acc += __half2float(h[(size_t)(r + 2) * 128 + j]);
        acc += __half2float(h[(size_t)(r + 3) * 128 + j]);
    }
    for (; r < end; r++) acc += __half2float(h[(size_t)r * 128 + j]);
    float c = fmaxf((float)(end - beg), 1.0f);
    gs[j] = acc / c;
    __syncthreads();

    float a1 = bf1[j];
#pragma unroll 8
    for (int k = 0; k < 128; k++) a1 += gs[k] * Wf1[k * 128 + j];
    float hid = fmaxf(a1, 0.0f);
    red[j] = hid * Wf2[j];
    __syncthreads();
    for (int s = 64; s > 0; s >>= 1) {
        if (j < s) red[j] += red[j + s];
        __syncthreads();
    }
    if (j == 0) out[g] = 1.0f / (1.0f + expf(-(red[0] + bf2[0])));
}

// ---------------- launch --------------------------------------------------------------
extern "C" void kernel_launch(void* const* d_in, const int* in_sizes, int n_in,
                              void* d_out, int out_size) {
    const float* x = (const float*)d_in[0];
    const int* el = (const int*)d_in[1];
    const int* batch = (const int*)d_in[2];
    WPtrs wp;
    const float* bb[5];
    for (int i = 0; i < 5; i++) {
        wp.p[2 * i]     = (const float*)d_in[3 + 3 * i];   // Wl
        wp.p[2 * i + 1] = (const float*)d_in[4 + 3 * i];   // Wr
        bb[i] = (const float*)d_in[5 + 3 * i];
    }
    const float* Wf1 = (const float*)d_in[18];
    const float* bf1 = (const float*)d_in[19];
    const float* Wf2 = (const float*)d_in[20];
    const float* bf2 = (const float*)d_in[21];
    float* out = (float*)d_out;

    __half *hh, *aggh, *wcat;
    int* cntn;
    cudaGetSymbolAddress((void**)&hh, g_hh);
    cudaGetSymbolAddress((void**)&aggh, g_aggh);
    cudaGetSymbolAddress((void**)&wcat, g_wcat);
    cudaGetSymbolAddress((void**)&cntn, g_cntn);

    static int init_done = 0;
    static cudaStream_t s1 = nullptr;
    static cudaEvent_t evF, evJ;
    const int dyn_smem = 3 * 128 * APITCH * 2;  // 104448 B
    if (!init_done) {
        cudaFuncSetAttribute(gemm_mma, cudaFuncAttributeMaxDynamicSharedMemorySize, dyn_smem);
        cudaStreamCreateWithFlags(&s1, cudaStreamNonBlocking);
        cudaEventCreateWithFlags(&evF, cudaEventDisableTiming);
        cudaEventCreateWithFlags(&evJ, cudaEventDisableTiming);
        init_done = 1;
    }

    // fork: prep (x->fp16, W->fp16) on side stream; CSR build on main
    cudaEventRecord(evF, 0);
    cudaStreamWaitEvent(s1, evF, 0);
    prep_kernel<<<(Nn * Hh / 2 + 255) / 256, 256, 0, s1>>>(x, wp);

    cudaMemsetAsync(cntn, 0, Nn * sizeof(int), 0);
    hist_kernel<<<(Ee / 2 + 255) / 256, 256>>>((const int4*)el);
    scan1_kernel<<<NSCAN_BLK, 1024>>>();
    scan3_kernel<<<(Nn + 255) / 256, 256>>>();
    fill_kernel<<<(Ee / 2 + 255) / 256, 256>>>((const int4*)el);

    // join: layers need both prep and CSR
    cudaEventRecord(evJ, s1);
    cudaStreamWaitEvent(0, evJ, 0);

    // 5 layers: gather -> persistent 2-tile tensor-core GEMM (in-place hh)
    for (int l = 0; l < 5; l++) {
        gather_kernel<<<(Nn * 16 + 255) / 256, 256>>>(hh);
        gemm_mma<<<NG2, 256, dyn_smem>>>(aggh, hh, wcat + (size_t)l * 256 * 128,
                                         bb[l], hh);
    }

    // fused segmented mean pool + MLP head
    pool_mlp_kernel<<<Gg, 128>>>(hh, batch, Wf1, bf1, Wf2, bf2, out);
}

// round 16
// speedup vs baseline: 1.0548x; 1.0548x over previous
#include <cuda_runtime.h>
#include <cuda_fp16.h>
#include <math.h>
#include <stdint.h>

#define Nn 50000
#define Ee 800000
#define Hh 128
#define Gg 128
#define NSCAN_BLK 49        // ceil(50000/1024)
#define NG_GEMM 391         // ceil(50000/128)
#define NWCAT (5 * 256 * 128)
#define APITCH 136          // 128 + 8 halves pad: conflict-free ldmatrix

// ---------------- scratch (allocation-free: __device__ globals) --------------
__device__ __half g_hh[Nn * Hh];      // fp16 activations (in-place across layers)
__device__ __half g_aggh[Nn * Hh];    // fp16 agg
__device__ __half g_wcat[NWCAT];      // fp16 [layer][k=256][n=128]
__device__ float  g_invdeg[Nn];
__device__ int    g_cntn[Nn];
__device__ int    g_scan[Nn];
__device__ int    g_bsum[NSCAN_BLK];
__device__ int    g_rowptr[Nn + 1];
__device__ int    g_cursor[Nn];
__device__ int    g_srcidx[Ee];

struct WPtrs { const float* p[10]; };

// ---------------- PTX wrappers -------------------------------------------------
__device__ __forceinline__ uint32_t smem_u32(const void* p) {
    uint32_t a;
    asm("{ .reg .u64 t; cvta.to.shared.u64 t, %1; cvt.u32.u64 %0, t; }"
        : "=r"(a) : "l"(p));
    return a;
}
__device__ __forceinline__ void ldsm_x4(uint32_t& r0, uint32_t& r1,
                                        uint32_t& r2, uint32_t& r3, uint32_t addr) {
    asm volatile("ldmatrix.sync.aligned.m8n8.x4.shared.b16 {%0,%1,%2,%3}, [%4];"
                 : "=r"(r0), "=r"(r1), "=r"(r2), "=r"(r3) : "r"(addr));
}
__device__ __forceinline__ void ldsm_x4t(uint32_t& r0, uint32_t& r1,
                                         uint32_t& r2, uint32_t& r3, uint32_t addr) {
    asm volatile("ldmatrix.sync.aligned.m8n8.x4.trans.shared.b16 {%0,%1,%2,%3}, [%4];"
                 : "=r"(r0), "=r"(r1), "=r"(r2), "=r"(r3) : "r"(addr));
}
__device__ __forceinline__ void mma16816(float* d, const uint32_t* a,
                                         uint32_t b0, uint32_t b1) {
    asm volatile(
        "mma.sync.aligned.m16n8k16.row.col.f32.f16.f16.f32 "
        "{%0,%1,%2,%3}, {%4,%5,%6,%7}, {%8,%9}, {%0,%1,%2,%3};"
        : "+f"(d[0]), "+f"(d[1]), "+f"(d[2]), "+f"(d[3])
        : "r"(a[0]), "r"(a[1]), "r"(a[2]), "r"(a[3]), "r"(b0), "r"(b1));
}
__device__ __forceinline__ void cp16(uint32_t saddr, const void* g) {
    asm volatile("cp.async.cg.shared.global [%0], [%1], 16;" :: "r"(saddr), "l"(g));
}
__device__ __forceinline__ void cp_commit() {
    asm volatile("cp.async.commit_group;" ::: "memory");
}
template <int N>
__device__ __forceinline__ void cp_wait() {
    asm volatile("cp.async.wait_group %0;" :: "n"(N) : "memory");
}

// ---------------- prep: x->fp16 + Wcat fp16 (side stream) ------------------------
__global__ void prep_kernel(const float* __restrict__ x, WPtrs wp) {
    int i = blockIdx.x * blockDim.x + threadIdx.x;
    if (i < Nn * Hh / 2) {
        float2 v = reinterpret_cast<const float2*>(x)[i];
        reinterpret_cast<__half2*>(g_hh)[i] = __floats2half2_rn(v.x, v.y);
    }
    if (i < NWCAT) {
        int l = i >> 15;
        int rem = i & 32767;
        int k = rem >> 7, n = rem & 127;
        const float* W = (k < 128) ? wp.p[2 * l] : wp.p[2 * l + 1];
        g_wcat[i] = __float2half_rn(W[(k & 127) * 128 + n]);
    }
}

// ---------------- CSR build (exact R10 versions) ----------------------------------
__global__ void hist_kernel(const int4* __restrict__ el2) {
    int t = blockIdx.x * blockDim.x + threadIdx.x;
    if (t < Ee / 2) {
        int4 e2 = el2[t];       // two edges: (x,y),(z,w)
        atomicAdd(&g_cntn[e2.y], 1);
        atomicAdd(&g_cntn[e2.w], 1);
    }
}
__global__ void scan1_kernel() {
    __shared__ int sh[1024];
    int tid = threadIdx.x;
    int i = blockIdx.x * 1024 + tid;
    int v = (i < Nn) ? g_cntn[i] : 0;
    sh[tid] = v;
    __syncthreads();
    for (int off = 1; off < 1024; off <<= 1) {
        int t = (tid >= off) ? sh[tid - off] : 0;
        __syncthreads();
        sh[tid] += t;
        __syncthreads();
    }
    if (i < Nn) g_scan[i] = sh[tid];
    if (tid == 1023) g_bsum[blockIdx.x] = sh[1023];
}
__global__ void scan3_kernel() {
    __shared__ int soff[NSCAN_BLK + 1];
    int tid = threadIdx.x;
    if (tid == 0) {
        int run = 0;
        for (int b = 0; b < NSCAN_BLK; b++) { soff[b] = run; run += g_bsum[b]; }
    }
    __syncthreads();
    int i = blockIdx.x * blockDim.x + tid;
    if (i < Nn) {
        int v = g_cntn[i];
        int excl = g_scan[i] - v + soff[i >> 10];
        g_rowptr[i] = excl;
        g_cursor[i] = excl;
        g_invdeg[i] = 1.0f / fmaxf((float)v, 1.0f);
    }
    if (i == 0) g_rowptr[Nn] = Ee;
}
__global__ void fill_kernel(const int4* __restrict__ el2) {
    int t = blockIdx.x * blockDim.x + threadIdx.x;
    if (t < Ee / 2) {
        int4 e2 = el2[t];
        int p0 = atomicAdd(&g_cursor[e2.y], 1);
        g_srcidx[p0] = e2.x;
        int p1 = atomicAdd(&g_cursor[e2.w], 1);
        g_srcidx[p1] = e2.z;
    }
}

// ---------------- neighbor gather: 16 lanes x 16B per row (R10 exact) -------------
__device__ __forceinline__ void acc_add8(float* a, uint4 v) {
    __half2 h0 = *reinterpret_cast<__half2*>(&v.x);
    __half2 h1 = *reinterpret_cast<__half2*>(&v.y);
    __half2 h2 = *reinterpret_cast<__half2*>(&v.z);
    __half2 h3 = *reinterpret_cast<__half2*>(&v.w);
    float2 f0 = __half22float2(h0), f1 = __half22float2(h1);
    float2 f2 = __half22float2(h2), f3 = __half22float2(h3);
    a[0] += f0.x; a[1] += f0.y; a[2] += f1.x; a[3] += f1.y;
    a[4] += f2.x; a[5] += f2.y; a[6] += f3.x; a[7] += f3.y;
}
__global__ void __launch_bounds__(256)
gather_kernel(const __half* __restrict__ hh) {
    int t = blockIdx.x * blockDim.x + threadIdx.x;
    int node = t >> 4;
    if (node >= Nn) return;
    int lane16 = t & 15;

    int beg = g_rowptr[node], end = g_rowptr[node + 1];
    float acc[8] = {0.f, 0.f, 0.f, 0.f, 0.f, 0.f, 0.f, 0.f};
    int i = beg;
    for (; i + 3 < end; i += 4) {
        int s0 = g_srcidx[i],     s1 = g_srcidx[i + 1];
        int s2 = g_srcidx[i + 2], s3 = g_srcidx[i + 3];
        uint4 v0 = reinterpret_cast<const uint4*>(hh + (size_t)s0 * Hh)[lane16];
        uint4 v1 = reinterpret_cast<const uint4*>(hh + (size_t)s1 * Hh)[lane16];
        uint4 v2 = reinterpret_cast<const uint4*>(hh + (size_t)s2 * Hh)[lane16];
        uint4 v3 = reinterpret_cast<const uint4*>(hh + (size_t)s3 * Hh)[lane16];
        acc_add8(acc, v0); acc_add8(acc, v1); acc_add8(acc, v2); acc_add8(acc, v3);
    }
    for (; i < end; i++) {
        uint4 v0 = reinterpret_cast<const uint4*>(hh + (size_t)g_srcidx[i] * Hh)[lane16];
        acc_add8(acc, v0);
    }
    float inv = g_invdeg[node];
    __half2 p0 = __floats2half2_rn(acc[0] * inv, acc[1] * inv);
    __half2 p1 = __floats2half2_rn(acc[2] * inv, acc[3] * inv);
    __half2 p2 = __floats2half2_rn(acc[4] * inv, acc[5] * inv);
    __half2 p3 = __floats2half2_rn(acc[6] * inv, acc[7] * inv);
    uint4 u;
    u.x = *reinterpret_cast<uint32_t*>(&p0);
    u.y = *reinterpret_cast<uint32_t*>(&p1);
    u.z = *reinterpret_cast<uint32_t*>(&p2);
    u.w = *reinterpret_cast<uint32_t*>(&p3);
    reinterpret_cast<uint4*>(g_aggh + (size_t)node * Hh)[lane16] = u;
}

// ---------------- tensor-core GEMM with 4-chunk cp.async pipeline -----------------
// h' = relu([agg|h] @ Wcat + b). K=256 in 2 stages; each stage split into two
// K=64 half-chunks (A: k-column halves; W: k-row halves). All loads except the
// first chunk are hidden under MMA compute. Compute mapping identical to R10.
__global__ void __launch_bounds__(256, 2)
gemm_mma(const __half* __restrict__ Ah, const __half* __restrict__ Hf,
         const __half* __restrict__ Wc, const float* __restrict__ bias,
         __half* __restrict__ Hout) {
    extern __shared__ __half smem[];
    __half* As = smem;                   // [128][APITCH]
    __half* Ws = smem + 128 * APITCH;    // [128][APITCH]
    __shared__ float sbias[128];

    int tid = threadIdx.x;
    int lane = tid & 31;
    int wid = tid >> 5;
    int wrow = wid & 3;
    int wcol = wid >> 2;
    int n0 = blockIdx.x * 128;

    if (tid < 128) sbias[tid] = bias[tid];

    float acc[2][8][4];
#pragma unroll
    for (int mt = 0; mt < 2; mt++)
#pragma unroll
        for (int nt = 0; nt < 8; nt++)
#pragma unroll
            for (int q = 0; q < 4; q++) acc[mt][nt][q] = 0.f;

    uint32_t as_u = smem_u32(As);
    uint32_t ws_u = smem_u32(Ws);

    int c8 = tid & 15;       // fixed 16B-chunk column per thread
    int rbase = tid >> 4;    // row base (0..15), rows rbase + rep*16

    // load one half-chunk of (A, W) for a stage via cp.async; one commit group.
    // h=0: A k-cols 0..63 (c8 0..7), W k-rows 0..63 (rep 0..3)
    // h=1: A k-cols 64..127 (c8 8..15), W k-rows 64..127 (rep 4..7)
    auto load_chunk = [&](const __half* Asrc, const __half* Wsrc, int h) {
        if ((c8 >> 3) == h) {
#pragma unroll
            for (int rep = 0; rep < 8; rep++) {
                int r = rbase + rep * 16;
                int n = n0 + r; if (n >= Nn) n = Nn - 1;
                cp16(as_u + (uint32_t)(r * APITCH + c8 * 8) * 2,
                     Asrc + (size_t)n * 128 + c8 * 8);
            }
        }
#pragma unroll
        for (int rep = 0; rep < 4; rep++) {
            int r = rbase + (h * 4 + rep) * 16;
            cp16(ws_u + (uint32_t)(r * APITCH + c8 * 8) * 2,
                 Wsrc + (size_t)r * 128 + c8 * 8);
        }
        cp_commit();
    };

    // compute one half (kc chunk h*4 .. h*4+3); mapping identical to R10.
    auto compute_half = [&](int h) {
#pragma unroll
        for (int kcx = 0; kcx < 4; kcx++) {
            int k0 = (h * 4 + kcx) * 16;
            uint32_t a[2][4];
#pragma unroll
            for (int mt = 0; mt < 2; mt++) {
                int r = wrow * 32 + mt * 16 + (lane & 15);
                uint32_t addr = as_u + (uint32_t)(r * APITCH + k0 + (lane >> 4) * 8) * 2;
                ldsm_x4(a[mt][0], a[mt][1], a[mt][2], a[mt][3], addr);
            }
#pragma unroll
            for (int nt2 = 0; nt2 < 4; nt2++) {
                int kr = k0 + (lane & 15);
                int nc = wcol * 64 + nt2 * 16 + (lane >> 4) * 8;
                uint32_t addr = ws_u + (uint32_t)(kr * APITCH + nc) * 2;
                uint32_t b0, b1, b2, b3;
                ldsm_x4t(b0, b1, b2, b3, addr);
#pragma unroll
                for (int mt = 0; mt < 2; mt++) {
                    mma16816(acc[mt][nt2 * 2],     a[mt], b0, b1);
                    mma16816(acc[mt][nt2 * 2 + 1], a[mt], b2, b3);
                }
            }
        }
    };

    const __half* Wl = Wc;
    const __half* Wr = Wc + 128 * 128;

    load_chunk(Ah, Wl, 0);   // group 1: S0 first half
    load_chunk(Ah, Wl, 1);   // group 2: S0 second half
    cp_wait<1>();            // group 1 landed
    __syncthreads();
    compute_half(0);         // S0 kc0-3  (group 2 arrives underneath)
    __syncthreads();         // all warps done reading A-cols0-63 / W-rows0-63
    load_chunk(Hf, Wr, 0);   // group 3: S1 first half into freed regions
    cp_wait<1>();            // group 2 landed
    __syncthreads();
    compute_half(1);         // S0 kc4-7  (group 3 arrives underneath)
    __syncthreads();         // all warps done reading A-cols64-127 / W-rows64-127
    load_chunk(Hf, Wr, 1);   // group 4: S1 second half
    cp_wait<1>();            // group 3 landed
    __syncthreads();
    compute_half(0);         // S1 kc0-3  (group 4 arrives underneath)
    cp_wait<0>();            // group 4 landed
    __syncthreads();
    compute_half(1);         // S1 kc4-7

    // epilogue: bias + relu -> fp16 (in-place safe: CTA read-set == write-set)
#pragma unroll
    for (int mt = 0; mt < 2; mt++) {
        int r0 = n0 + wrow * 32 + mt * 16 + (lane >> 2);
#pragma unroll
        for (int nt = 0; nt < 8; nt++) {
            int col = wcol * 64 + nt * 8 + (lane & 3) * 2;
            float b0 = sbias[col], b1 = sbias[col + 1];
            float v0 = fmaxf(acc[mt][nt][0] + b0, 0.f);
            float v1 = fmaxf(acc[mt][nt][1] + b1, 0.f);
            float v2 = fmaxf(acc[mt][nt][2] + b0, 0.f);
            float v3 = fmaxf(acc[mt][nt][3] + b1, 0.f);
            if (r0 < Nn)
                *reinterpret_cast<__half2*>(Hout + (size_t)r0 * 128 + col) =
                    __floats2half2_rn(v0, v1);
            if (r0 + 8 < Nn)
                *reinterpret_cast<__half2*>(Hout + (size_t)(r0 + 8) * 128 + col) =
                    __floats2half2_rn(v2, v3);
        }
    }
}

// ---------------- fused pool + MLP head: one block per graph ----------------------
__global__ void pool_mlp_kernel(const __half* __restrict__ h,
                                const int* __restrict__ batch,
                                const float* __restrict__ Wf1,
                                const float* __restrict__ bf1,
                                const float* __restrict__ Wf2,
                                const float* __restrict__ bf2,
                                float* __restrict__ out) {
    __shared__ int sbeg, send;
    __shared__ float gs[128];
    __shared__ float red[128];
    int g = blockIdx.x;
    int j = threadIdx.x;
    if (j == 0) {
        int lo = 0, hi = Nn;
        while (lo < hi) { int mid = (lo + hi) >> 1; if (batch[mid] < g) lo = mid + 1; else hi = mid; }
        sbeg = lo;
        lo = 0; hi = Nn;
        while (lo < hi) { int mid = (lo + hi) >> 1; if (batch[mid] < g + 1) lo = mid + 1; else hi = mid; }
        send = lo;
    }
    __syncthreads();
    int beg = sbeg, end = send;
    float acc = 0.f;
    int r = beg;
    for (; r + 3 < end; r += 4) {
        acc += __half2float(h[(size_t)r * 128 + j]);
        acc += __half2float(h[(size_t)(r + 1) * 128 + j]);
        acc += __half2float(h[(size_t)(r + 2) * 128 + j]);
        acc += __half2float(h[(size_t)(r + 3) * 128 + j]);
    }
    for (; r < end; r++) acc += __half2float(h[(size_t)r * 128 + j]);
    float c = fmaxf((float)(end - beg), 1.0f);
    gs[j] = acc / c;
    __syncthreads();

    float a1 = bf1[j];
#pragma unroll 8
    for (int k = 0; k < 128; k++) a1 += gs[k] * Wf1[k * 128 + j];
    float hid = fmaxf(a1, 0.0f);
    red[j] = hid * Wf2[j];
    __syncthreads();
    for (int s = 64; s > 0; s >>= 1) {
        if (j < s) red[j] += red[j + s];
        __syncthreads();
    }
    if (j == 0) out[g] = 1.0f / (1.0f + expf(-(red[0] + bf2[0])));
}

// ---------------- launch --------------------------------------------------------------
extern "C" void kernel_launch(void* const* d_in, const int* in_sizes, int n_in,
                              void* d_out, int out_size) {
    const float* x = (const float*)d_in[0];
    const int* el = (const int*)d_in[1];
    const int* batch = (const int*)d_in[2];
    WPtrs wp;
    const float* bb[5];
    for (int i = 0; i < 5; i++) {
        wp.p[2 * i]     = (const float*)d_in[3 + 3 * i];   // Wl
        wp.p[2 * i + 1] = (const float*)d_in[4 + 3 * i];   // Wr
        bb[i] = (const float*)d_in[5 + 3 * i];
    }
    const float* Wf1 = (const float*)d_in[18];
    const float* bf1 = (const float*)d_in[19];
    const float* Wf2 = (const float*)d_in[20];
    const float* bf2 = (const float*)d_in[21];
    float* out = (float*)d_out;

    __half *hh, *aggh, *wcat;
    int* cntn;
    cudaGetSymbolAddress((void**)&hh, g_hh);
    cudaGetSymbolAddress((void**)&aggh, g_aggh);
    cudaGetSymbolAddress((void**)&wcat, g_wcat);
    cudaGetSymbolAddress((void**)&cntn, g_cntn);

    static int init_done = 0;
    static cudaStream_t s1 = nullptr;
    static cudaEvent_t evF, evJ;
    const int dyn_smem = 2 * 128 * APITCH * 2;  // 69632 B
    if (!init_done) {
        cudaFuncSetAttribute(gemm_mma, cudaFuncAttributeMaxDynamicSharedMemorySize, dyn_smem);
        cudaStreamCreateWithFlags(&s1, cudaStreamNonBlocking);
        cudaEventCreateWithFlags(&evF, cudaEventDisableTiming);
        cudaEventCreateWithFlags(&evJ, cudaEventDisableTiming);
        init_done = 1;
    }

    // fork: prep (x->fp16, W->fp16) on side stream; CSR build on main
    cudaEventRecord(evF, 0);
    cudaStreamWaitEvent(s1, evF, 0);
    prep_kernel<<<(Nn * Hh / 2 + 255) / 256, 256, 0, s1>>>(x, wp);

    cudaMemsetAsync(cntn, 0, Nn * sizeof(int), 0);
    hist_kernel<<<(Ee / 2 + 255) / 256, 256>>>((const int4*)el);
    scan1_kernel<<<NSCAN_BLK, 1024>>>();
    scan3_kernel<<<(Nn + 255) / 256, 256>>>();
    fill_kernel<<<(Ee / 2 + 255) / 256, 256>>>((const int4*)el);

    // join: layers need both prep and CSR
    cudaEventRecord(evJ, s1);
    cudaStreamWaitEvent(0, evJ, 0);

    // 5 layers: gather -> tensor-core GEMM (in-place hh update)
    for (int l = 0; l < 5; l++) {
        gather_kernel<<<(Nn * 16 + 255) / 256, 256>>>(hh);
        gemm_mma<<<NG_GEMM, 256, dyn_smem>>>(aggh, hh, wcat + (size_t)l * 256 * 128,
                                             bb[l], hh);
    }

    // fused segmented mean pool + MLP head
    pool_mlp_kernel<<<Gg, 128>>>(hh, batch, Wf1, bf1, Wf2, bf2, out);
}

// round 17
// speedup vs baseline: 1.0884x; 1.0318x over previous
#include <cuda_runtime.h>
#include <cuda_fp16.h>
#include <math.h>
#include <stdint.h>

#define Nn 50000
#define Ee 800000
#define Hh 128
#define Gg 128
#define NSCAN_BLK 49        // ceil(50000/1024)
#define NG_GEMM 391         // ceil(50000/128)
#define NWCAT (5 * 256 * 128)
#define APITCH 136          // 128 + 8 halves pad: conflict-free ldmatrix

// ---------------- scratch (allocation-free: __device__ globals) --------------
__device__ __half g_hh[Nn * Hh];      // fp16 activations (in-place across layers)
__device__ __half g_aggh[Nn * Hh];    // fp16 agg
__device__ __half g_wcat[NWCAT];      // fp16 [layer][k=256][n=128]
__device__ float  g_invdeg[Nn];
__device__ int    g_cntn[Nn];
__device__ int    g_scan[Nn];
__device__ int    g_bsum[NSCAN_BLK];
__device__ int    g_rowptr[Nn + 1];
__device__ int    g_cursor[Nn];
__device__ int    g_srcidx[Ee];

struct WPtrs { const float* p[10]; };

// ---------------- PTX wrappers -------------------------------------------------
__device__ __forceinline__ uint32_t smem_u32(const void* p) {
    uint32_t a;
    asm("{ .reg .u64 t; cvta.to.shared.u64 t, %1; cvt.u32.u64 %0, t; }"
        : "=r"(a) : "l"(p));
    return a;
}
__device__ __forceinline__ void ldsm_x4(uint32_t& r0, uint32_t& r1,
                                        uint32_t& r2, uint32_t& r3, uint32_t addr) {
    asm volatile("ldmatrix.sync.aligned.m8n8.x4.shared.b16 {%0,%1,%2,%3}, [%4];"
                 : "=r"(r0), "=r"(r1), "=r"(r2), "=r"(r3) : "r"(addr));
}
__device__ __forceinline__ void ldsm_x4t(uint32_t& r0, uint32_t& r1,
                                         uint32_t& r2, uint32_t& r3, uint32_t addr) {
    asm volatile("ldmatrix.sync.aligned.m8n8.x4.trans.shared.b16 {%0,%1,%2,%3}, [%4];"
                 : "=r"(r0), "=r"(r1), "=r"(r2), "=r"(r3) : "r"(addr));
}
__device__ __forceinline__ void mma16816(float* d, const uint32_t* a,
                                         uint32_t b0, uint32_t b1) {
    asm volatile(
        "mma.sync.aligned.m16n8k16.row.col.f32.f16.f16.f32 "
        "{%0,%1,%2,%3}, {%4,%5,%6,%7}, {%8,%9}, {%0,%1,%2,%3};"
        : "+f"(d[0]), "+f"(d[1]), "+f"(d[2]), "+f"(d[3])
        : "r"(a[0]), "r"(a[1]), "r"(a[2]), "r"(a[3]), "r"(b0), "r"(b1));
}

// ---------------- prep: x->fp16 + Wcat fp16 (side stream) ------------------------
__global__ void prep_kernel(const float* __restrict__ x, WPtrs wp) {
    int i = blockIdx.x * blockDim.x + threadIdx.x;
    if (i < Nn * Hh / 2) {
        float2 v = reinterpret_cast<const float2*>(x)[i];
        reinterpret_cast<__half2*>(g_hh)[i] = __floats2half2_rn(v.x, v.y);
    }
    if (i < NWCAT) {
        int l = i >> 15;
        int rem = i & 32767;
        int k = rem >> 7, n = rem & 127;
        const float* W = (k < 128) ? wp.p[2 * l] : wp.p[2 * l + 1];
        g_wcat[i] = __float2half_rn(W[(k & 127) * 128 + n]);
    }
}

// ---------------- CSR build (2-edge ILP in hist/fill) -----------------------------
__global__ void hist_kernel(const int4* __restrict__ el2) {
    int t = blockIdx.x * blockDim.x + threadIdx.x;
    if (t < Ee / 2) {
        int4 e2 = el2[t];       // two edges: (x,y),(z,w)
        atomicAdd(&g_cntn[e2.y], 1);
        atomicAdd(&g_cntn[e2.w], 1);
    }
}
__global__ void scan1_kernel() {
    __shared__ int sh[1024];
    int tid = threadIdx.x;
    int i = blockIdx.x * 1024 + tid;
    int v = (i < Nn) ? g_cntn[i] : 0;
    sh[tid] = v;
    __syncthreads();
    for (int off = 1; off < 1024; off <<= 1) {
        int t = (tid >= off) ? sh[tid - off] : 0;
        __syncthreads();
        sh[tid] += t;
        __syncthreads();
    }
    if (i < Nn) g_scan[i] = sh[tid];
    if (tid == 1023) g_bsum[blockIdx.x] = sh[1023];
}
__global__ void scan3_kernel() {
    __shared__ int soff[NSCAN_BLK + 1];
    int tid = threadIdx.x;
    if (tid == 0) {
        int run = 0;
        for (int b = 0; b < NSCAN_BLK; b++) { soff[b] = run; run += g_bsum[b]; }
    }
    __syncthreads();
    int i = blockIdx.x * blockDim.x + tid;
    if (i < Nn) {
        int v = g_cntn[i];
        int excl = g_scan[i] - v + soff[i >> 10];
        g_rowptr[i] = excl;
        g_cursor[i] = excl;
        g_invdeg[i] = 1.0f / fmaxf((float)v, 1.0f);
    }
    if (i == 0) g_rowptr[Nn] = Ee;
}
__global__ void fill_kernel(const int4* __restrict__ el2) {
    int t = blockIdx.x * blockDim.x + threadIdx.x;
    if (t < Ee / 2) {
        int4 e2 = el2[t];
        int p0 = atomicAdd(&g_cursor[e2.y], 1);
        g_srcidx[p0] = e2.x;
        int p1 = atomicAdd(&g_cursor[e2.w], 1);
        g_srcidx[p1] = e2.z;
    }
}

// ---------------- neighbor gather: 16 lanes x 16B per row ------------------------
__device__ __forceinline__ void acc_add8(float* a, uint4 v) {
    __half2 h0 = *reinterpret_cast<__half2*>(&v.x);
    __half2 h1 = *reinterpret_cast<__half2*>(&v.y);
    __half2 h2 = *reinterpret_cast<__half2*>(&v.z);
    __half2 h3 = *reinterpret_cast<__half2*>(&v.w);
    float2 f0 = __half22float2(h0), f1 = __half22float2(h1);
    float2 f2 = __half22float2(h2), f3 = __half22float2(h3);
    a[0] += f0.x; a[1] += f0.y; a[2] += f1.x; a[3] += f1.y;
    a[4] += f2.x; a[5] += f2.y; a[6] += f3.x; a[7] += f3.y;
}
__global__ void __launch_bounds__(256)
gather_kernel(const __half* __restrict__ hh) {
    int t = blockIdx.x * blockDim.x + threadIdx.x;
    int node = t >> 4;
    if (node >= Nn) return;
    int lane16 = t & 15;

    int beg = g_rowptr[node], end = g_rowptr[node + 1];
    float acc[8] = {0.f, 0.f, 0.f, 0.f, 0.f, 0.f, 0.f, 0.f};
    int i = beg;
    for (; i + 3 < end; i += 4) {
        int s0 = g_srcidx[i],     s1 = g_srcidx[i + 1];
        int s2 = g_srcidx[i + 2], s3 = g_srcidx[i + 3];
        uint4 v0 = reinterpret_cast<const uint4*>(hh + (size_t)s0 * Hh)[lane16];
        uint4 v1 = reinterpret_cast<const uint4*>(hh + (size_t)s1 * Hh)[lane16];
        uint4 v2 = reinterpret_cast<const uint4*>(hh + (size_t)s2 * Hh)[lane16];
        uint4 v3 = reinterpret_cast<const uint4*>(hh + (size_t)s3 * Hh)[lane16];
        acc_add8(acc, v0); acc_add8(acc, v1); acc_add8(acc, v2); acc_add8(acc, v3);
    }
    for (; i < end; i++) {
        uint4 v0 = reinterpret_cast<const uint4*>(hh + (size_t)g_srcidx[i] * Hh)[lane16];
        acc_add8(acc, v0);
    }
    float inv = g_invdeg[node];
    __half2 p0 = __floats2half2_rn(acc[0] * inv, acc[1] * inv);
    __half2 p1 = __floats2half2_rn(acc[2] * inv, acc[3] * inv);
    __half2 p2 = __floats2half2_rn(acc[4] * inv, acc[5] * inv);
    __half2 p3 = __floats2half2_rn(acc[6] * inv, acc[7] * inv);
    uint4 u;
    u.x = *reinterpret_cast<uint32_t*>(&p0);
    u.y = *reinterpret_cast<uint32_t*>(&p1);
    u.z = *reinterpret_cast<uint32_t*>(&p2);
    u.w = *reinterpret_cast<uint32_t*>(&p3);
    reinterpret_cast<uint4*>(g_aggh + (size_t)node * Hh)[lane16] = u;
}

// ---------------- tensor-core GEMM: h' = relu([agg|h] @ Wcat + b) ----------------
// K=256 in 2 stages. CTA 128x128, 8 warps. (the proven 257.9us configuration)
__global__ void __launch_bounds__(256, 2)
gemm_mma(const __half* __restrict__ Ah, const __half* __restrict__ Hf,
         const __half* __restrict__ Wc, const float* __restrict__ bias,
         __half* __restrict__ Hout) {
    extern __shared__ __half smem[];
    __half* As = smem;                   // [128][APITCH]
    __half* Ws = smem + 128 * APITCH;    // [128][APITCH]
    __shared__ float sbias[128];

    int tid = threadIdx.x;
    int lane = tid & 31;
    int wid = tid >> 5;
    int wrow = wid & 3;
    int wcol = wid >> 2;
    int n0 = blockIdx.x * 128;

    if (tid < 128) sbias[tid] = bias[tid];

    float acc[2][8][4];
#pragma unroll
    for (int mt = 0; mt < 2; mt++)
#pragma unroll
        for (int nt = 0; nt < 8; nt++)
#pragma unroll
            for (int q = 0; q < 4; q++) acc[mt][nt][q] = 0.f;

    uint32_t as_u = smem_u32(As);
    uint32_t ws_u = smem_u32(Ws);

#pragma unroll
    for (int s = 0; s < 2; s++) {
        const __half* Asrc = s ? Hf : Ah;
        const __half* Wsrc = Wc + s * 128 * 128;
#pragma unroll
        for (int rep = 0; rep < 8; rep++) {
            int c = tid + rep * 256;
            int r = c >> 4, c8 = c & 15;
            int n = n0 + r; if (n >= Nn) n = Nn - 1;
            *reinterpret_cast<uint4*>(As + r * APITCH + c8 * 8) =
                *reinterpret_cast<const uint4*>(Asrc + (size_t)n * 128 + c8 * 8);
            *reinterpret_cast<uint4*>(Ws + r * APITCH + c8 * 8) =
                *reinterpret_cast<const uint4*>(Wsrc + (size_t)r * 128 + c8 * 8);
        }
        __syncthreads();

#pragma unroll
        for (int kc = 0; kc < 8; kc++) {
            int k0 = kc * 16;
            uint32_t a[2][4];
#pragma unroll
            for (int mt = 0; mt < 2; mt++) {
                int r = wrow * 32 + mt * 16 + (lane & 15);
                uint32_t addr = as_u + (uint32_t)(r * APITCH + k0 + (lane >> 4) * 8) * 2;
                ldsm_x4(a[mt][0], a[mt][1], a[mt][2], a[mt][3], addr);
            }
#pragma unroll
            for (int nt2 = 0; nt2 < 4; nt2++) {
                int kr = k0 + (lane & 15);
                int nc = wcol * 64 + nt2 * 16 + (lane >> 4) * 8;
                uint32_t addr = ws_u + (uint32_t)(kr * APITCH + nc) * 2;
                uint32_t b0, b1, b2, b3;
                ldsm_x4t(b0, b1, b2, b3, addr);
#pragma unroll
                for (int mt = 0; mt < 2; mt++) {
                    mma16816(acc[mt][nt2 * 2],     a[mt], b0, b1);
                    mma16816(acc[mt][nt2 * 2 + 1], a[mt], b2, b3);
                }
            }
        }
        __syncthreads();
    }

    // epilogue: bias + relu -> fp16 (in-place safe: CTA read-set == write-set)
#pragma unroll
    for (int mt = 0; mt < 2; mt++) {
        int r0 = n0 + wrow * 32 + mt * 16 + (lane >> 2);
#pragma unroll
        for (int nt = 0; nt < 8; nt++) {
            int col = wcol * 64 + nt * 8 + (lane & 3) * 2;
            float b0 = sbias[col], b1 = sbias[col + 1];
            float v0 = fmaxf(acc[mt][nt][0] + b0, 0.f);
            float v1 = fmaxf(acc[mt][nt][1] + b1, 0.f);
            float v2 = fmaxf(acc[mt][nt][2] + b0, 0.f);
            float v3 = fmaxf(acc[mt][nt][3] + b1, 0.f);
            if (r0 < Nn)
                *reinterpret_cast<__half2*>(Hout + (size_t)r0 * 128 + col) =
                    __floats2half2_rn(v0, v1);
            if (r0 + 8 < Nn)
                *reinterpret_cast<__half2*>(Hout + (size_t)(r0 + 8) * 128 + col) =
                    __floats2half2_rn(v2, v3);
        }
    }
}

// ---------------- fused pool + MLP head: one block per graph ----------------------
__global__ void pool_mlp_kernel(const __half* __restrict__ h,
                                const int* __restrict__ batch,
                                const float* __restrict__ Wf1,
                                const float* __restrict__ bf1,
                                const float* __restrict__ Wf2,
                                const float* __restrict__ bf2,
                                float* __restrict__ out) {
    __shared__ int sbeg, send;
    __shared__ float gs[128];
    __shared__ float red[128];
    int g = blockIdx.x;
    int j = threadIdx.x;
    if (j == 0) {
        int lo = 0, hi = Nn;
        while (lo < hi) { int mid = (lo + hi) >> 1; if (batch[mid] < g) lo = mid + 1; else hi = mid; }
        sbeg = lo;
        lo = 0; hi = Nn;
        while (lo < hi) { int mid = (lo + hi) >> 1; if (batch[mid] < g + 1) lo = mid + 1; else hi = mid; }
        send = lo;
    }
    __syncthreads();
    int beg = sbeg, end = send;
    float acc = 0.f;
    int r = beg;
    for (; r + 3 < end; r += 4) {
        acc += __half2float(h[(size_t)r * 128 + j]);
        acc += __half2float(h[(size_t)(r + 1) * 128 + j]);
        acc += __half2float(h[(size_t)(r + 2) * 128 + j]);
        acc += __half2float(h[(size_t)(r + 3) * 128 + j]);
    }
    for (; r < end; r++) acc += __half2float(h[(size_t)r * 128 + j]);
    float c = fmaxf((float)(end - beg), 1.0f);
    gs[j] = acc / c;
    __syncthreads();

    float a1 = bf1[j];
#pragma unroll 8
    for (int k = 0; k < 128; k++) a1 += gs[k] * Wf1[k * 128 + j];
    float hid = fmaxf(a1, 0.0f);
    red[j] = hid * Wf2[j];
    __syncthreads();
    for (int s = 64; s > 0; s >>= 1) {
        if (j < s) red[j] += red[j + s];
        __syncthreads();
    }
    if (j == 0) out[g] = 1.0f / (1.0f + expf(-(red[0] + bf2[0])));
}

// ---------------- launch --------------------------------------------------------------
extern "C" void kernel_launch(void* const* d_in, const int* in_sizes, int n_in,
                              void* d_out, int out_size) {
    const float* x = (const float*)d_in[0];
    const int* el = (const int*)d_in[1];
    const int* batch = (const int*)d_in[2];
    WPtrs wp;
    const float* bb[5];
    for (int i = 0; i < 5; i++) {
        wp.p[2 * i]     = (const float*)d_in[3 + 3 * i];   // Wl
        wp.p[2 * i + 1] = (const float*)d_in[4 + 3 * i];   // Wr
        bb[i] = (const float*)d_in[5 + 3 * i];
    }
    const float* Wf1 = (const float*)d_in[18];
    const float* bf1 = (const float*)d_in[19];
    const float* Wf2 = (const float*)d_in[20];
    const float* bf2 = (const float*)d_in[21];
    float* out = (float*)d_out;

    __half *hh, *aggh, *wcat;
    int* cntn;
    cudaGetSymbolAddress((void**)&hh, g_hh);
    cudaGetSymbolAddress((void**)&aggh, g_aggh);
    cudaGetSymbolAddress((void**)&wcat, g_wcat);
    cudaGetSymbolAddress((void**)&cntn, g_cntn);

    static int init_done = 0;
    static cudaStream_t s1 = nullptr;
    static cudaEvent_t evF, evJ;
    const int dyn_smem = 2 * 128 * APITCH * 2;  // 69632 B
    if (!init_done) {
        cudaFuncSetAttribute(gemm_mma, cudaFuncAttributeMaxDynamicSharedMemorySize, dyn_smem);
        cudaStreamCreateWithFlags(&s1, cudaStreamNonBlocking);
        cudaEventCreateWithFlags(&evF, cudaEventDisableTiming);
        cudaEventCreateWithFlags(&evJ, cudaEventDisableTiming);
        init_done = 1;
    }

    // fork: prep (x->fp16, W->fp16) on side stream; CSR build on main
    cudaEventRecord(evF, 0);
    cudaStreamWaitEvent(s1, evF, 0);
    prep_kernel<<<(Nn * Hh / 2 + 255) / 256, 256, 0, s1>>>(x, wp);

    cudaMemsetAsync(cntn, 0, Nn * sizeof(int), 0);
    hist_kernel<<<(Ee / 2 + 255) / 256, 256>>>((const int4*)el);
    scan1_kernel<<<NSCAN_BLK, 1024>>>();
    scan3_kernel<<<(Nn + 255) / 256, 256>>>();
    fill_kernel<<<(Ee / 2 + 255) / 256, 256>>>((const int4*)el);

    // join: layers need both prep and CSR
    cudaEventRecord(evJ, s1);
    cudaStreamWaitEvent(0, evJ, 0);

    // 5 layers: gather -> tensor-core GEMM (in-place hh update)
    for (int l = 0; l < 5; l++) {
        gather_kernel<<<(Nn * 16 + 255) / 256, 256>>>(hh);
        gemm_mma<<<NG_GEMM, 256, dyn_smem>>>(aggh, hh, wcat + (size_t)l * 256 * 128,
                                             bb[l], hh);
    }

    // fused segmented mean pool + MLP head
    pool_mlp_kernel<<<Gg, 128>>>(hh, batch, Wf1, bf1, Wf2, bf2, out);
}